// round 14
// baseline (speedup 1.0000x reference)
#include <cuda_runtime.h>
#include <cuda_fp16.h>
#include <mma.h>
#include <cstdint>

using namespace nvcuda;

#define NN 50000
#define NN_PAD 50048   // 391 * 128
#define NE 800000
#define IND 64
#define HD 128
#define OD 64
#define BN_EPS 1e-5f
#define NB 49   // ceil(NN/1024)

typedef unsigned long long ull;

// ---- scratch (__device__ globals; zero-init at load; zero-invariants kept) ----
__device__ __align__(256) int    g_degi[NN];        // zero-invariant (restored in k_scan3)
__device__ __align__(256) int    g_off[NN + 1];
__device__ __align__(256) int    g_rank[NE];        // edge rank within its dst bucket
__device__ __align__(256) int    g_esrc[NE];
__device__ __align__(256) int    g_bsums[NB];
__device__ __align__(256) float  g_deginv[NN];
__device__ __align__(256) __half g_xh[NN_PAD * IND];    // fp16 x (pad rows stay 0)
__device__ __align__(256) __half g_agg1h[NN_PAD * IND]; // fp16 mean-agg of x (pad 0)
__device__ __align__(256) float  g_hpre[NN_PAD * HD];   // fp32 pre-BN layer-1 out
__device__ __align__(256) __half g_hrelu[NN_PAD * HD];  // fp16 relu(bn(hpre)) (pad 0)
__device__ __align__(256) __half g_agg2h[NN_PAD * HD];  // fp16 mean-agg of hrelu (pad 0)
__device__ __align__(256) float  g_bnsum[HD];       // zero-invariant (restored in k_agg2)
__device__ __align__(256) float  g_bnsq[HD];        // zero-invariant (restored in k_agg2)
// fp16 weight matrices for WMMA, row-major [k][j]
__device__ __align__(256) __half g_wb1[HD * HD];    // k:[W1l rows 0..63 | W1r rows 64..127], N=128
__device__ __align__(256) __half g_wb2[2 * HD * OD];// k:[W2l rows 0..127 | W2r rows 128..255], N=64

__device__ __forceinline__ ull pack2(float x, float y) {
    ull r;
    asm("mov.b64 %0, {%1,%2};" : "=l"(r) : "f"(x), "f"(y));
    return r;
}
__device__ __forceinline__ float2 unpack2(ull v) {
    float2 r;
    asm("mov.b64 {%0,%1}, %2;" : "=f"(r.x), "=f"(r.y) : "l"(v));
    return r;
}
__device__ __forceinline__ void fadd2(ull& d, ull a) {
    asm("add.rn.f32x2 %0, %0, %1;" : "+l"(d) : "l"(a));
}
__device__ __forceinline__ void acc_u4(ull* acc, uint4 u) {
    float2 f0 = __half22float2(*(__half2*)&u.x);
    float2 f1 = __half22float2(*(__half2*)&u.y);
    float2 f2 = __half22float2(*(__half2*)&u.z);
    float2 f3 = __half22float2(*(__half2*)&u.w);
    fadd2(acc[0], pack2(f0.x, f0.y));
    fadd2(acc[1], pack2(f1.x, f1.y));
    fadd2(acc[2], pack2(f2.x, f2.y));
    fadd2(acc[3], pack2(f3.x, f3.y));
}
__device__ __forceinline__ uint4 f8_to_h8(const float* s) {
    __half2 a = __floats2half2_rn(s[0], s[1]);
    __half2 b = __floats2half2_rn(s[2], s[3]);
    __half2 c = __floats2half2_rn(s[4], s[5]);
    __half2 d = __floats2half2_rn(s[6], s[7]);
    uint4 u;
    u.x = *(unsigned int*)&a; u.y = *(unsigned int*)&b;
    u.z = *(unsigned int*)&c; u.w = *(unsigned int*)&d;
    return u;
}

// ---- fused prep + degree histogram (stores per-edge rank = old count) ----
__global__ void k_prepdeg(const float* __restrict__ x,
                          const float* __restrict__ W1l, const float* __restrict__ W1r,
                          const float* __restrict__ W2l, const float* __restrict__ W2r,
                          const int* __restrict__ dst) {
    int t = blockIdx.x * blockDim.x + threadIdx.x;
    int stride = gridDim.x * blockDim.x;
    for (int i = t; i < HD * HD; i += stride) {
        int k = i >> 7, j = i & 127;
        float w = (k < IND) ? W1l[k * HD + j] : W1r[(k - IND) * HD + j];
        g_wb1[i] = __float2half_rn(w);
    }
    for (int i = t; i < 2 * HD * OD; i += stride) {
        int k = i >> 6, j = i & 63;
        float w = (k < HD) ? W2l[k * OD + j] : W2r[(k - HD) * OD + j];
        g_wb2[i] = __float2half_rn(w);
    }
    for (int i = t; i < NN * IND / 8; i += stride) {
        float4 v0 = ((const float4*)x)[2 * i];
        float4 v1 = ((const float4*)x)[2 * i + 1];
        float f[8] = {v0.x, v0.y, v0.z, v0.w, v1.x, v1.y, v1.z, v1.w};
        ((uint4*)g_xh)[i] = f8_to_h8(f);
    }
    for (int i = t; i < NE / 4; i += stride) {
        int4 d = ((const int4*)dst)[i];
        int4 r;
        r.x = atomicAdd(&g_degi[d.x], 1);
        r.y = atomicAdd(&g_degi[d.y], 1);
        r.z = atomicAdd(&g_degi[d.z], 1);
        r.w = atomicAdd(&g_degi[d.w], 1);
        ((int4*)g_rank)[i] = r;
    }
}

// ---- scan stage 1 ----
__global__ void k_scan1() {
    __shared__ int ws[32];
    int tid = threadIdx.x, lane = tid & 31, w = tid >> 5;
    int i = blockIdx.x * 1024 + tid;
    int v = (i < NN) ? g_degi[i] : 0;
    int s = v;
#pragma unroll
    for (int o = 1; o < 32; o <<= 1) {
        int tt = __shfl_up_sync(0xffffffffu, s, o);
        if (lane >= o) s += tt;
    }
    if (lane == 31) ws[w] = s;
    __syncthreads();
    if (w == 0) {
        int t2 = ws[lane];
#pragma unroll
        for (int o = 1; o < 32; o <<= 1) {
            int tt = __shfl_up_sync(0xffffffffu, t2, o);
            if (lane >= o) t2 += tt;
        }
        ws[lane] = t2;
    }
    __syncthreads();
    int excl = ((w > 0) ? ws[w - 1] : 0) + s - v;
    if (i < NN) g_off[i] = excl;
    if (tid == 1023) g_bsums[blockIdx.x] = ws[31];
}

// ---- scan stage 2: prefix + deginv + restore g_degi zeros ----
__global__ void k_scan3() {
    __shared__ int sb[64];
    int tid = threadIdx.x;
    if (tid < 64) {
        int lane = tid & 31;
        int v = (tid < NB) ? g_bsums[tid] : 0;
        int s = v;
#pragma unroll
        for (int o = 1; o < 32; o <<= 1) {
            int tt = __shfl_up_sync(0xffffffffu, s, o);
            if (lane >= o) s += tt;
        }
        sb[tid] = s - v;
    }
    __syncthreads();
    if (tid >= 32 && tid < 64) {
        int w0tot = sb[31] + g_bsums[31];
        sb[tid] += w0tot;
    }
    __syncthreads();
    int pref = sb[blockIdx.x];
    int i = blockIdx.x * 1024 + tid;
    if (i < NN) {
        g_off[i] += pref;
        int d = g_degi[i];
        g_deginv[i] = (d > 0) ? (1.0f / (float)d) : 0.0f;
        g_degi[i] = 0;
    }
    if (i == NN) g_off[NN] = NE;
}

// ---- CSR fill, atomic-free, 1 edge/thread (max latency hiding) ----
__global__ void k_fill(const int* __restrict__ src, const int* __restrict__ dst) {
    int e = blockIdx.x * blockDim.x + threadIdx.x;
    if (e >= NE) return;
    int d = dst[e];
    g_esrc[g_off[d] + g_rank[e]] = src[e];
}

// ---- layer-1 mean aggregation: 8 threads/node, f32x2 accumulate, fp16 out ----
__global__ void k_agg1() {
    int t = blockIdx.x * blockDim.x + threadIdx.x;
    int node = t >> 3, c = t & 7;
    if (node >= NN) return;
    int beg = g_off[node], end = g_off[node + 1];
    ull acc[4] = {0ull, 0ull, 0ull, 0ull};
    int j = beg;
    for (; j + 2 <= end; j += 2) {
        int s0 = g_esrc[j], s1 = g_esrc[j + 1];
        uint4 u0 = ((const uint4*)g_xh)[s0 * 8 + c];
        uint4 u1 = ((const uint4*)g_xh)[s1 * 8 + c];
        acc_u4(acc, u0);
        acc_u4(acc, u1);
    }
    if (j < end)
        acc_u4(acc, ((const uint4*)g_xh)[g_esrc[j] * 8 + c]);
    float di = g_deginv[node];
    float2 p0 = unpack2(acc[0]), p1 = unpack2(acc[1]);
    float2 p2 = unpack2(acc[2]), p3 = unpack2(acc[3]);
    float f[8] = {p0.x * di, p0.y * di, p1.x * di, p1.y * di,
                  p2.x * di, p2.y * di, p3.x * di, p3.y * di};
    ((uint4*)g_agg1h)[node * 8 + c] = f8_to_h8(f);
}

// ==== layer-1 dense via WMMA + fused BN column stats ====
// hpre = [agg1h|xh] @ [W1l;W1r]; b1 omitted (BN shift-invariant).
// Tail: block re-reads its own L2-hot 128x128 tile, accumulates BN partials.
__global__ void __launch_bounds__(256) k_lin1w() {
    __shared__ __half smB[HD * HD];   // 32 KB: B1 staged
    const int tid = threadIdx.x;
    const int warp = tid >> 5;
    const int blk0 = blockIdx.x * 128;
    const int m0 = blk0 + warp * 16;

    for (int i = tid; i < HD * HD / 8; i += 256)
        ((uint4*)smB)[i] = ((const uint4*)g_wb1)[i];
    __syncthreads();

    wmma::fragment<wmma::accumulator, 16, 16, 16, float> acc[8];
#pragma unroll
    for (int n = 0; n < 8; n++) wmma::fill_fragment(acc[n], 0.0f);

#pragma unroll
    for (int k = 0; k < 4; k++) {   // K 0..63 from agg1h
        wmma::fragment<wmma::matrix_a, 16, 16, 16, __half, wmma::row_major> af;
        wmma::load_matrix_sync(af, g_agg1h + (size_t)m0 * IND + k * 16, IND);
#pragma unroll
        for (int n = 0; n < 8; n++) {
            wmma::fragment<wmma::matrix_b, 16, 16, 16, __half, wmma::row_major> bf;
            wmma::load_matrix_sync(bf, smB + (k * 16) * HD + n * 16, HD);
            wmma::mma_sync(acc[n], af, bf, acc[n]);
        }
    }
#pragma unroll
    for (int k = 0; k < 4; k++) {   // K 64..127 from xh
        wmma::fragment<wmma::matrix_a, 16, 16, 16, __half, wmma::row_major> af;
        wmma::load_matrix_sync(af, g_xh + (size_t)m0 * IND + k * 16, IND);
#pragma unroll
        for (int n = 0; n < 8; n++) {
            wmma::fragment<wmma::matrix_b, 16, 16, 16, __half, wmma::row_major> bf;
            wmma::load_matrix_sync(bf, smB + (64 + k * 16) * HD + n * 16, HD);
            wmma::mma_sync(acc[n], af, bf, acc[n]);
        }
    }
#pragma unroll
    for (int n = 0; n < 8; n++)
        wmma::store_matrix_sync(g_hpre + (size_t)m0 * HD + n * 16, acc[n], HD,
                                wmma::mem_row_major);

    // ---- fused BN partial stats: re-read own tile (L2-hot) ----
    __syncthreads();   // orders the block's global stores before re-read
    const int j = tid & 127;          // column
    const int rbase = (tid >> 7) * 64; // row half: 0 or 64
    float s = 0.f, sq = 0.f;
#pragma unroll 4
    for (int r = 0; r < 64; r++) {
        int node = blk0 + rbase + r;
        if (node < NN) {
            float v = g_hpre[(size_t)node * HD + j];
            s += v;
            sq += v * v;
        }
    }
    atomicAdd(&g_bnsum[j], s);
    atomicAdd(&g_bnsq[j], sq);
}

// ---- BN finalize + relu: g_hrelu = fp16(relu(bn(hpre))) ----
__global__ void k_hrelu(const float* __restrict__ gamma,
                        const float* __restrict__ beta) {
    __shared__ float s_sc[HD];
    __shared__ float s_sh[HD];
    int tid = threadIdx.x;
    if (tid < HD) {
        float mu = g_bnsum[tid] * (1.0f / NN);
        float var = g_bnsq[tid] * (1.0f / NN) - mu * mu;
        float sc = gamma[tid] * rsqrtf(var + BN_EPS);
        s_sc[tid] = sc;
        s_sh[tid] = beta[tid] - mu * sc;
    }
    __syncthreads();
    int i = blockIdx.x * blockDim.x + tid;
    if (i >= NN * HD / 4) return;
    int c = i & 31;
    float4 h = ((const float4*)g_hpre)[i];
    float4 sc = *(const float4*)&s_sc[4 * c];
    float4 sh = *(const float4*)&s_sh[4 * c];
    float v0 = fmaxf(fmaf(h.x, sc.x, sh.x), 0.f);
    float v1 = fmaxf(fmaf(h.y, sc.y, sh.y), 0.f);
    float v2 = fmaxf(fmaf(h.z, sc.z, sh.z), 0.f);
    float v3 = fmaxf(fmaf(h.w, sc.w, sh.w), 0.f);
    __half2 a = __floats2half2_rn(v0, v1);
    __half2 b = __floats2half2_rn(v2, v3);
    uint2 u;
    u.x = *(unsigned int*)&a;
    u.y = *(unsigned int*)&b;
    ((uint2*)g_hrelu)[i] = u;
}

// ---- layer-2 mean aggregation: fp16 out; restores g_bnsum/g_bnsq zeros ----
__global__ void k_agg2() {
    int t = blockIdx.x * blockDim.x + threadIdx.x;
    if (t < HD) { g_bnsum[t] = 0.f; g_bnsq[t] = 0.f; }
    int node = t >> 4, c = t & 15;
    if (node >= NN) return;
    int beg = g_off[node], end = g_off[node + 1];
    ull acc[4] = {0ull, 0ull, 0ull, 0ull};
    int j = beg;
    for (; j + 2 <= end; j += 2) {
        int s0 = g_esrc[j], s1 = g_esrc[j + 1];
        uint4 u0 = ((const uint4*)g_hrelu)[s0 * 16 + c];
        uint4 u1 = ((const uint4*)g_hrelu)[s1 * 16 + c];
        acc_u4(acc, u0);
        acc_u4(acc, u1);
    }
    if (j < end)
        acc_u4(acc, ((const uint4*)g_hrelu)[g_esrc[j] * 16 + c]);
    float di = g_deginv[node];
    float2 p0 = unpack2(acc[0]), p1 = unpack2(acc[1]);
    float2 p2 = unpack2(acc[2]), p3 = unpack2(acc[3]);
    float f[8] = {p0.x * di, p0.y * di, p1.x * di, p1.y * di,
                  p2.x * di, p2.y * di, p3.x * di, p3.y * di};
    ((uint4*)g_agg2h)[node * 16 + c] = f8_to_h8(f);
}

// ==== layer-2 dense via WMMA: out = [agg2h|hrelu] @ [W2l;W2r] + b2 ====
__global__ void __launch_bounds__(256) k_lin2w(const float* __restrict__ b2,
                                               float* __restrict__ out) {
    __shared__ __half smB[2 * HD * OD];   // 32 KB: B2 staged (reused for C staging)
    const int tid = threadIdx.x;
    const int warp = tid >> 5, lane = tid & 31;
    const int m0 = blockIdx.x * 128 + warp * 16;

    for (int i = tid; i < 2 * HD * OD / 8; i += 256)
        ((uint4*)smB)[i] = ((const uint4*)g_wb2)[i];
    __syncthreads();

    wmma::fragment<wmma::accumulator, 16, 16, 16, float> acc[4];
#pragma unroll
    for (int n = 0; n < 4; n++) wmma::fill_fragment(acc[n], 0.0f);

#pragma unroll
    for (int k = 0; k < 8; k++) {   // K 0..127 from agg2h
        wmma::fragment<wmma::matrix_a, 16, 16, 16, __half, wmma::row_major> af;
        wmma::load_matrix_sync(af, g_agg2h + (size_t)m0 * HD + k * 16, HD);
#pragma unroll
        for (int n = 0; n < 4; n++) {
            wmma::fragment<wmma::matrix_b, 16, 16, 16, __half, wmma::row_major> bf;
            wmma::load_matrix_sync(bf, smB + (k * 16) * OD + n * 16, OD);
            wmma::mma_sync(acc[n], af, bf, acc[n]);
        }
    }
#pragma unroll
    for (int k = 0; k < 8; k++) {   // K 128..255 from hrelu
        wmma::fragment<wmma::matrix_a, 16, 16, 16, __half, wmma::row_major> af;
        wmma::load_matrix_sync(af, g_hrelu + (size_t)m0 * HD + k * 16, HD);
#pragma unroll
        for (int n = 0; n < 4; n++) {
            wmma::fragment<wmma::matrix_b, 16, 16, 16, __half, wmma::row_major> bf;
            wmma::load_matrix_sync(bf, smB + (128 + k * 16) * OD + n * 16, OD);
            wmma::mma_sync(acc[n], af, bf, acc[n]);
        }
    }

    // reuse smB as per-warp fp32 C staging (16x64 floats per warp = 4 KB)
    __syncthreads();
    float* cw = (float*)smB + warp * 16 * OD;
#pragma unroll
    for (int n = 0; n < 4; n++)
        wmma::store_matrix_sync(cw + n * 16, acc[n], OD, wmma::mem_row_major);
    __syncwarp();

    float bj0 = b2[lane];
    float bj1 = b2[lane + 32];
#pragma unroll
    for (int r = 0; r < 16; r++) {
        int node = m0 + r;
        if (node < NN) {
            out[node * OD + lane]      = cw[r * OD + lane] + bj0;
            out[node * OD + lane + 32] = cw[r * OD + lane + 32] + bj1;
        }
    }
}

extern "C" void kernel_launch(void* const* d_in, const int* in_sizes, int n_in,
                              void* d_out, int out_size) {
    const float* x     = (const float*)d_in[0];
    const int*   ei    = (const int*)d_in[1];
    const float* W1l   = (const float*)d_in[2];
    const float* b1    = (const float*)d_in[3];
    const float* W1r   = (const float*)d_in[4];
    const float* gamma = (const float*)d_in[5];
    const float* beta  = (const float*)d_in[6];
    const float* W2l   = (const float*)d_in[7];
    const float* b2    = (const float*)d_in[8];
    const float* W2r   = (const float*)d_in[9];
    float* out = (float*)d_out;
    (void)b1;   // BN makes the layer-1 bias a no-op

    const int* src = ei;
    const int* dst = ei + NE;

    k_prepdeg<<<2048, 256>>>(x, W1l, W1r, W2l, W2r, dst);
    k_scan1<<<NB, 1024>>>();
    k_scan3<<<NB, 1024>>>();
    k_fill<<<(NE + 255) / 256, 256>>>(src, dst);
    k_agg1<<<(NN * 8 + 255) / 256, 256>>>();
    k_lin1w<<<NN_PAD / 128, 256>>>();
    k_hrelu<<<(NN * HD / 4 + 255) / 256, 256>>>(gamma, beta);
    k_agg2<<<(NN * 16 + 255) / 256, 256>>>();
    k_lin2w<<<NN_PAD / 128, 256>>>(b2, out);
}

// round 15
// speedup vs baseline: 1.0442x; 1.0442x over previous
#include <cuda_runtime.h>
#include <cuda_fp16.h>
#include <mma.h>
#include <cstdint>

using namespace nvcuda;

#define NN 50000
#define NN_PAD 50048   // 391 * 128
#define NE 800000
#define IND 64
#define HD 128
#define OD 64
#define BN_EPS 1e-5f
#define NB 49   // ceil(NN/1024)

typedef unsigned long long ull;

// ---- scratch (__device__ globals; zero-init at load; zero-invariants kept) ----
__device__ __align__(256) int    g_degi[NN];        // zero-invariant (restored in k_scan3)
__device__ __align__(256) int    g_off[NN + 1];
__device__ __align__(256) int    g_rank[NE];        // edge rank within its dst bucket
__device__ __align__(256) int    g_esrc[NE];
__device__ __align__(256) int    g_bsums[NB];
__device__ __align__(256) float  g_deginv[NN];
__device__ __align__(256) __half g_xh[NN_PAD * IND];    // fp16 x (pad rows stay 0)
__device__ __align__(256) __half g_agg1h[NN_PAD * IND]; // fp16 mean-agg of x (pad 0)
__device__ __align__(256) float  g_hpre[NN_PAD * HD];   // fp32 pre-BN layer-1 out
__device__ __align__(256) __half g_hrelu[NN_PAD * HD];  // fp16 relu(bn(hpre)) (pad 0)
__device__ __align__(256) __half g_agg2h[NN_PAD * HD];  // fp16 mean-agg of hrelu (pad 0)
__device__ __align__(256) float  g_bnsum[HD];       // zero-invariant (restored in k_agg2)
__device__ __align__(256) float  g_bnsq[HD];        // zero-invariant (restored in k_agg2)
// fp16 weight matrices for WMMA, row-major [k][j]
__device__ __align__(256) __half g_wb1[HD * HD];    // k:[W1l rows 0..63 | W1r rows 64..127], N=128
__device__ __align__(256) __half g_wb2[2 * HD * OD];// k:[W2l rows 0..127 | W2r rows 128..255], N=64

__device__ __forceinline__ ull pack2(float x, float y) {
    ull r;
    asm("mov.b64 %0, {%1,%2};" : "=l"(r) : "f"(x), "f"(y));
    return r;
}
__device__ __forceinline__ float2 unpack2(ull v) {
    float2 r;
    asm("mov.b64 {%0,%1}, %2;" : "=f"(r.x), "=f"(r.y) : "l"(v));
    return r;
}
__device__ __forceinline__ void fadd2(ull& d, ull a) {
    asm("add.rn.f32x2 %0, %0, %1;" : "+l"(d) : "l"(a));
}
__device__ __forceinline__ void acc_u4(ull* acc, uint4 u) {
    float2 f0 = __half22float2(*(__half2*)&u.x);
    float2 f1 = __half22float2(*(__half2*)&u.y);
    float2 f2 = __half22float2(*(__half2*)&u.z);
    float2 f3 = __half22float2(*(__half2*)&u.w);
    fadd2(acc[0], pack2(f0.x, f0.y));
    fadd2(acc[1], pack2(f1.x, f1.y));
    fadd2(acc[2], pack2(f2.x, f2.y));
    fadd2(acc[3], pack2(f3.x, f3.y));
}
__device__ __forceinline__ uint4 f8_to_h8(const float* s) {
    __half2 a = __floats2half2_rn(s[0], s[1]);
    __half2 b = __floats2half2_rn(s[2], s[3]);
    __half2 c = __floats2half2_rn(s[4], s[5]);
    __half2 d = __floats2half2_rn(s[6], s[7]);
    uint4 u;
    u.x = *(unsigned int*)&a; u.y = *(unsigned int*)&b;
    u.z = *(unsigned int*)&c; u.w = *(unsigned int*)&d;
    return u;
}

// ---- fused prep + degree histogram (stores per-edge rank = old count) ----
__global__ void k_prepdeg(const float* __restrict__ x,
                          const float* __restrict__ W1l, const float* __restrict__ W1r,
                          const float* __restrict__ W2l, const float* __restrict__ W2r,
                          const int* __restrict__ dst) {
    int t = blockIdx.x * blockDim.x + threadIdx.x;
    int stride = gridDim.x * blockDim.x;
    for (int i = t; i < HD * HD; i += stride) {
        int k = i >> 7, j = i & 127;
        float w = (k < IND) ? W1l[k * HD + j] : W1r[(k - IND) * HD + j];
        g_wb1[i] = __float2half_rn(w);
    }
    for (int i = t; i < 2 * HD * OD; i += stride) {
        int k = i >> 6, j = i & 63;
        float w = (k < HD) ? W2l[k * OD + j] : W2r[(k - HD) * OD + j];
        g_wb2[i] = __float2half_rn(w);
    }
    for (int i = t; i < NN * IND / 8; i += stride) {
        float4 v0 = ((const float4*)x)[2 * i];
        float4 v1 = ((const float4*)x)[2 * i + 1];
        float f[8] = {v0.x, v0.y, v0.z, v0.w, v1.x, v1.y, v1.z, v1.w};
        ((uint4*)g_xh)[i] = f8_to_h8(f);
    }
    for (int i = t; i < NE / 4; i += stride) {
        int4 d = ((const int4*)dst)[i];
        int4 r;
        r.x = atomicAdd(&g_degi[d.x], 1);
        r.y = atomicAdd(&g_degi[d.y], 1);
        r.z = atomicAdd(&g_degi[d.z], 1);
        r.w = atomicAdd(&g_degi[d.w], 1);
        ((int4*)g_rank)[i] = r;
    }
}

// ---- scan stage 1 ----
__global__ void k_scan1() {
    __shared__ int ws[32];
    int tid = threadIdx.x, lane = tid & 31, w = tid >> 5;
    int i = blockIdx.x * 1024 + tid;
    int v = (i < NN) ? g_degi[i] : 0;
    int s = v;
#pragma unroll
    for (int o = 1; o < 32; o <<= 1) {
        int tt = __shfl_up_sync(0xffffffffu, s, o);
        if (lane >= o) s += tt;
    }
    if (lane == 31) ws[w] = s;
    __syncthreads();
    if (w == 0) {
        int t2 = ws[lane];
#pragma unroll
        for (int o = 1; o < 32; o <<= 1) {
            int tt = __shfl_up_sync(0xffffffffu, t2, o);
            if (lane >= o) t2 += tt;
        }
        ws[lane] = t2;
    }
    __syncthreads();
    int excl = ((w > 0) ? ws[w - 1] : 0) + s - v;
    if (i < NN) g_off[i] = excl;
    if (tid == 1023) g_bsums[blockIdx.x] = ws[31];
}

// ---- scan stage 2: prefix + deginv + restore g_degi zeros ----
__global__ void k_scan3() {
    __shared__ int sb[64];
    int tid = threadIdx.x;
    if (tid < 64) {
        int lane = tid & 31;
        int v = (tid < NB) ? g_bsums[tid] : 0;
        int s = v;
#pragma unroll
        for (int o = 1; o < 32; o <<= 1) {
            int tt = __shfl_up_sync(0xffffffffu, s, o);
            if (lane >= o) s += tt;
        }
        sb[tid] = s - v;
    }
    __syncthreads();
    if (tid >= 32 && tid < 64) {
        int w0tot = sb[31] + g_bsums[31];
        sb[tid] += w0tot;
    }
    __syncthreads();
    int pref = sb[blockIdx.x];
    int i = blockIdx.x * 1024 + tid;
    if (i < NN) {
        g_off[i] += pref;
        int d = g_degi[i];
        g_deginv[i] = (d > 0) ? (1.0f / (float)d) : 0.0f;
        g_degi[i] = 0;
    }
    if (i == NN) g_off[NN] = NE;
}

// ---- CSR fill, atomic-free, 1 edge/thread (measured best) ----
__global__ void k_fill(const int* __restrict__ src, const int* __restrict__ dst) {
    int e = blockIdx.x * blockDim.x + threadIdx.x;
    if (e >= NE) return;
    int d = dst[e];
    g_esrc[g_off[d] + g_rank[e]] = src[e];
}

// ---- layer-1 mean aggregation: 8 threads/node, f32x2 accumulate, fp16 out ----
__global__ void k_agg1() {
    int t = blockIdx.x * blockDim.x + threadIdx.x;
    int node = t >> 3, c = t & 7;
    if (node >= NN) return;
    int beg = g_off[node], end = g_off[node + 1];
    ull acc[4] = {0ull, 0ull, 0ull, 0ull};
    int j = beg;
    for (; j + 2 <= end; j += 2) {
        int s0 = g_esrc[j], s1 = g_esrc[j + 1];
        uint4 u0 = ((const uint4*)g_xh)[s0 * 8 + c];
        uint4 u1 = ((const uint4*)g_xh)[s1 * 8 + c];
        acc_u4(acc, u0);
        acc_u4(acc, u1);
    }
    if (j < end)
        acc_u4(acc, ((const uint4*)g_xh)[g_esrc[j] * 8 + c]);
    float di = g_deginv[node];
    float2 p0 = unpack2(acc[0]), p1 = unpack2(acc[1]);
    float2 p2 = unpack2(acc[2]), p3 = unpack2(acc[3]);
    float f[8] = {p0.x * di, p0.y * di, p1.x * di, p1.y * di,
                  p2.x * di, p2.y * di, p3.x * di, p3.y * di};
    ((uint4*)g_agg1h)[node * 8 + c] = f8_to_h8(f);
}

// ==== layer-1 dense via WMMA (HMMA): hpre = [agg1h|xh] @ [W1l;W1r]
//      b1 omitted: BatchNorm is invariant to a per-feature constant shift. ====
__global__ void __launch_bounds__(256) k_lin1w() {
    __shared__ __half smB[HD * HD];   // 32 KB: B1 staged
    const int tid = threadIdx.x;
    const int warp = tid >> 5;
    const int m0 = blockIdx.x * 128 + warp * 16;

    for (int i = tid; i < HD * HD / 8; i += 256)
        ((uint4*)smB)[i] = ((const uint4*)g_wb1)[i];
    __syncthreads();

    wmma::fragment<wmma::accumulator, 16, 16, 16, float> acc[8];
#pragma unroll
    for (int n = 0; n < 8; n++) wmma::fill_fragment(acc[n], 0.0f);

#pragma unroll
    for (int k = 0; k < 4; k++) {   // K 0..63 from agg1h
        wmma::fragment<wmma::matrix_a, 16, 16, 16, __half, wmma::row_major> af;
        wmma::load_matrix_sync(af, g_agg1h + (size_t)m0 * IND + k * 16, IND);
#pragma unroll
        for (int n = 0; n < 8; n++) {
            wmma::fragment<wmma::matrix_b, 16, 16, 16, __half, wmma::row_major> bf;
            wmma::load_matrix_sync(bf, smB + (k * 16) * HD + n * 16, HD);
            wmma::mma_sync(acc[n], af, bf, acc[n]);
        }
    }
#pragma unroll
    for (int k = 0; k < 4; k++) {   // K 64..127 from xh
        wmma::fragment<wmma::matrix_a, 16, 16, 16, __half, wmma::row_major> af;
        wmma::load_matrix_sync(af, g_xh + (size_t)m0 * IND + k * 16, IND);
#pragma unroll
        for (int n = 0; n < 8; n++) {
            wmma::fragment<wmma::matrix_b, 16, 16, 16, __half, wmma::row_major> bf;
            wmma::load_matrix_sync(bf, smB + (64 + k * 16) * HD + n * 16, HD);
            wmma::mma_sync(acc[n], af, bf, acc[n]);
        }
    }
#pragma unroll
    for (int n = 0; n < 8; n++)
        wmma::store_matrix_sync(g_hpre + (size_t)m0 * HD + n * 16, acc[n], HD,
                                wmma::mem_row_major);
}

// ---- BN column statistics over hpre (separate full-occupancy pass) ----
__global__ void k_bnstat() {
    int j = threadIdx.x & 127;
    int stream = blockIdx.x * 2 + (threadIdx.x >> 7);
    float s = 0.f, sq = 0.f;
    for (int n = stream; n < NN; n += 256) {
        float v = g_hpre[n * HD + j];
        s += v;
        sq += v * v;
    }
    atomicAdd(&g_bnsum[j], s);
    atomicAdd(&g_bnsq[j], sq);
}

// ---- BN finalize + relu: g_hrelu = fp16(relu(bn(hpre))) ----
__global__ void k_hrelu(const float* __restrict__ gamma,
                        const float* __restrict__ beta) {
    __shared__ float s_sc[HD];
    __shared__ float s_sh[HD];
    int tid = threadIdx.x;
    if (tid < HD) {
        float mu = g_bnsum[tid] * (1.0f / NN);
        float var = g_bnsq[tid] * (1.0f / NN) - mu * mu;
        float sc = gamma[tid] * rsqrtf(var + BN_EPS);
        s_sc[tid] = sc;
        s_sh[tid] = beta[tid] - mu * sc;
    }
    __syncthreads();
    int i = blockIdx.x * blockDim.x + tid;
    if (i >= NN * HD / 4) return;
    int c = i & 31;
    float4 h = ((const float4*)g_hpre)[i];
    float4 sc = *(const float4*)&s_sc[4 * c];
    float4 sh = *(const float4*)&s_sh[4 * c];
    float v0 = fmaxf(fmaf(h.x, sc.x, sh.x), 0.f);
    float v1 = fmaxf(fmaf(h.y, sc.y, sh.y), 0.f);
    float v2 = fmaxf(fmaf(h.z, sc.z, sh.z), 0.f);
    float v3 = fmaxf(fmaf(h.w, sc.w, sh.w), 0.f);
    __half2 a = __floats2half2_rn(v0, v1);
    __half2 b = __floats2half2_rn(v2, v3);
    uint2 u;
    u.x = *(unsigned int*)&a;
    u.y = *(unsigned int*)&b;
    ((uint2*)g_hrelu)[i] = u;
}

// ---- layer-2 mean aggregation: fp16 out; restores g_bnsum/g_bnsq zeros ----
__global__ void k_agg2() {
    int t = blockIdx.x * blockDim.x + threadIdx.x;
    if (t < HD) { g_bnsum[t] = 0.f; g_bnsq[t] = 0.f; }
    int node = t >> 4, c = t & 15;
    if (node >= NN) return;
    int beg = g_off[node], end = g_off[node + 1];
    ull acc[4] = {0ull, 0ull, 0ull, 0ull};
    int j = beg;
    for (; j + 2 <= end; j += 2) {
        int s0 = g_esrc[j], s1 = g_esrc[j + 1];
        uint4 u0 = ((const uint4*)g_hrelu)[s0 * 16 + c];
        uint4 u1 = ((const uint4*)g_hrelu)[s1 * 16 + c];
        acc_u4(acc, u0);
        acc_u4(acc, u1);
    }
    if (j < end)
        acc_u4(acc, ((const uint4*)g_hrelu)[g_esrc[j] * 16 + c]);
    float di = g_deginv[node];
    float2 p0 = unpack2(acc[0]), p1 = unpack2(acc[1]);
    float2 p2 = unpack2(acc[2]), p3 = unpack2(acc[3]);
    float f[8] = {p0.x * di, p0.y * di, p1.x * di, p1.y * di,
                  p2.x * di, p2.y * di, p3.x * di, p3.y * di};
    ((uint4*)g_agg2h)[node * 16 + c] = f8_to_h8(f);
}

// ==== layer-2 dense via WMMA: out = [agg2h|hrelu] @ [W2l;W2r] + b2 ====
__global__ void __launch_bounds__(256) k_lin2w(const float* __restrict__ b2,
                                               float* __restrict__ out) {
    __shared__ __half smB[2 * HD * OD];   // 32 KB: B2 staged (reused for C staging)
    const int tid = threadIdx.x;
    const int warp = tid >> 5, lane = tid & 31;
    const int m0 = blockIdx.x * 128 + warp * 16;

    for (int i = tid; i < 2 * HD * OD / 8; i += 256)
        ((uint4*)smB)[i] = ((const uint4*)g_wb2)[i];
    __syncthreads();

    wmma::fragment<wmma::accumulator, 16, 16, 16, float> acc[4];
#pragma unroll
    for (int n = 0; n < 4; n++) wmma::fill_fragment(acc[n], 0.0f);

#pragma unroll
    for (int k = 0; k < 8; k++) {   // K 0..127 from agg2h
        wmma::fragment<wmma::matrix_a, 16, 16, 16, __half, wmma::row_major> af;
        wmma::load_matrix_sync(af, g_agg2h + (size_t)m0 * HD + k * 16, HD);
#pragma unroll
        for (int n = 0; n < 4; n++) {
            wmma::fragment<wmma::matrix_b, 16, 16, 16, __half, wmma::row_major> bf;
            wmma::load_matrix_sync(bf, smB + (k * 16) * OD + n * 16, OD);
            wmma::mma_sync(acc[n], af, bf, acc[n]);
        }
    }
#pragma unroll
    for (int k = 0; k < 8; k++) {   // K 128..255 from hrelu
        wmma::fragment<wmma::matrix_a, 16, 16, 16, __half, wmma::row_major> af;
        wmma::load_matrix_sync(af, g_hrelu + (size_t)m0 * HD + k * 16, HD);
#pragma unroll
        for (int n = 0; n < 4; n++) {
            wmma::fragment<wmma::matrix_b, 16, 16, 16, __half, wmma::row_major> bf;
            wmma::load_matrix_sync(bf, smB + (128 + k * 16) * OD + n * 16, OD);
            wmma::mma_sync(acc[n], af, bf, acc[n]);
        }
    }

    // reuse smB as per-warp fp32 C staging (16x64 floats per warp = 4 KB)
    __syncthreads();
    float* cw = (float*)smB + warp * 16 * OD;
#pragma unroll
    for (int n = 0; n < 4; n++)
        wmma::store_matrix_sync(cw + n * 16, acc[n], OD, wmma::mem_row_major);
    __syncwarp();

    float bj0 = b2[lane];
    float bj1 = b2[lane + 32];
#pragma unroll
    for (int r = 0; r < 16; r++) {
        int node = m0 + r;
        if (node < NN) {
            out[node * OD + lane]      = cw[r * OD + lane] + bj0;
            out[node * OD + lane + 32] = cw[r * OD + lane + 32] + bj1;
        }
    }
}

extern "C" void kernel_launch(void* const* d_in, const int* in_sizes, int n_in,
                              void* d_out, int out_size) {
    const float* x     = (const float*)d_in[0];
    const int*   ei    = (const int*)d_in[1];
    const float* W1l   = (const float*)d_in[2];
    const float* b1    = (const float*)d_in[3];
    const float* W1r   = (const float*)d_in[4];
    const float* gamma = (const float*)d_in[5];
    const float* beta  = (const float*)d_in[6];
    const float* W2l   = (const float*)d_in[7];
    const float* b2    = (const float*)d_in[8];
    const float* W2r   = (const float*)d_in[9];
    float* out = (float*)d_out;
    (void)b1;   // BN makes the layer-1 bias a no-op

    const int* src = ei;
    const int* dst = ei + NE;

    k_prepdeg<<<2048, 256>>>(x, W1l, W1r, W2l, W2r, dst);
    k_scan1<<<NB, 1024>>>();
    k_scan3<<<NB, 1024>>>();
    k_fill<<<(NE + 255) / 256, 256>>>(src, dst);
    k_agg1<<<(NN * 8 + 255) / 256, 256>>>();
    k_lin1w<<<NN_PAD / 128, 256>>>();
    k_bnstat<<<128, 256>>>();
    k_hrelu<<<(NN * HD / 4 + 255) / 256, 256>>>(gamma, beta);
    k_agg2<<<(NN * 16 + 255) / 256, 256>>>();
    k_lin2w<<<NN_PAD / 128, 256>>>(b2, out);
}